// round 9
// baseline (speedup 1.0000x reference)
#include <cuda_runtime.h>
#include <math.h>

// Problem geometry (fixed by reference): T=1e6, D=82, 256 groups
#define D        82
#define NGROUP   256
#define NSTAT    6            // count, Sx, Sy, Sxx, Syy, Sxy
#define TPB      96           // threads per block (3 warps)
#define ROWS     48           // rows per tile (half of TPB)
#define TILE_ELEMS (ROWS * D)        // 3936 floats = 15.75 KB
#define BLOCKS_PER_SM 6
#define MAX_GRID   (148 * BLOCKS_PER_SM)   // 888

// Zero-initialized at module load; finalize_kernel re-zeroes after use so
// every launch/replay starts from identical state.
__device__ double g_stats[NSTAT * NGROUP];

// Double-buffered persistent kernel at full occupancy: while tile k is
// computed out of one shared buffer, tile k+1 streams (coalesced float4
// LDGs) into the other. 6 blocks/SM x 3 warps = 18 warps/SM keep DRAM
// requests in flight continuously.
// Stats accumulate in float shared atomics (per-block partials over ~4
// rows/group -> fp32 exact enough), promoted to double at the single
// per-block global flush.
__global__ __launch_bounds__(TPB, BLOCKS_PER_SM)
void pred_stats_kernel(const float4* __restrict__ X1,
                       const float4* __restrict__ X2,
                       const float*  __restrict__ Y,
                       const float*  __restrict__ W,
                       const int*    __restrict__ mask,
                       float* __restrict__ pred_out,   // may be null
                       int T, int numTiles)
{
    __shared__ __align__(16) float sDiff[2][TILE_ELEMS];  // 31.5 KB
    __shared__ float sStat[NSTAT * NGROUP];               // 6 KB
    __shared__ float sW[D];

    const int tid = threadIdx.x;

    for (int i = tid; i < NSTAT * NGROUP; i += TPB) sStat[i] = 0.0f;
    if (tid < D) sW[tid] = W[tid];

    const int firstTile = blockIdx.x;

    // ---- stage helper ----
#define STAGE(tileIdx, buf)                                                  \
    do {                                                                     \
        const int _row0 = (tileIdx) * ROWS;                                  \
        const int _rows = min(ROWS, T - _row0);                              \
        const int _n4   = (_rows * D) / 4;                                   \
        const size_t _b4 = (size_t)_row0 * D / 4;                            \
        const float4* __restrict__ _A = X1 + _b4;                            \
        const float4* __restrict__ _B = X2 + _b4;                            \
        float4* __restrict__ _S = reinterpret_cast<float4*>(sDiff[buf]);     \
        _Pragma("unroll 5")                                                  \
        for (int _i = tid; _i < _n4; _i += TPB) {                            \
            float4 _a = _A[_i];                                              \
            float4 _b = _B[_i];                                              \
            float4 _d;                                                       \
            _d.x = _a.x - _b.x; _d.x *= _d.x;                                \
            _d.y = _a.y - _b.y; _d.y *= _d.y;                                \
            _d.z = _a.z - _b.z; _d.z *= _d.z;                                \
            _d.w = _a.w - _b.w; _d.w *= _d.w;                                \
            _S[_i] = _d;                                                     \
        }                                                                    \
    } while (0)

    __syncthreads();                 // sStat/sW init visible
    if (firstTile < numTiles) STAGE(firstTile, 0);   // prologue

    int k = 0;
    for (int tile = firstTile; tile < numTiles; tile += gridDim.x, k++) {
        const int cur = k & 1;
        const int row0 = tile * ROWS;
        const int rows = min(ROWS, T - row0);
        const int t    = row0 + tid;

        __syncthreads();   // buf[cur] staged; prior compute on buf[cur^1] done

        // This tile's Y/mask loads issue early (overlap with staging below)
        float yReg = 0.0f; int gReg = 0;
        if (tid < rows) { yReg = Y[t]; gReg = mask[t]; }

        // Stage NEXT tile into the other buffer (LDGs go out first)
        const int nextTile = tile + gridDim.x;
        if (nextTile < numTiles) STAGE(nextTile, cur ^ 1);

        // Compute current tile: one row per thread (tid < ROWS)
        if (tid < rows) {
            const float2* __restrict__ dd =
                reinterpret_cast<const float2*>(sDiff[cur] + tid * D);
            float s = 0.0f;
            #pragma unroll
            for (int i = 0; i < D / 2; i++) {
                float2 v = dd[i];
                s = fmaf(v.x, sW[2 * i],     s);
                s = fmaf(v.y, sW[2 * i + 1], s);
            }
            float x = sqrtf(s);
            if (pred_out) pred_out[t] = x;

            const int g = gReg;
            const float y = yReg;
            atomicAdd(&sStat[0 * NGROUP + g], 1.0f);
            atomicAdd(&sStat[1 * NGROUP + g], x);
            atomicAdd(&sStat[2 * NGROUP + g], y);
            atomicAdd(&sStat[3 * NGROUP + g], s);       // x*x == s (to rounding)
            atomicAdd(&sStat[4 * NGROUP + g], y * y);
            atomicAdd(&sStat[5 * NGROUP + g], x * y);
        }
    }
#undef STAGE

    __syncthreads();
    // One flush per persistent block: promote float partials to global doubles
    for (int i = tid; i < NSTAT * NGROUP; i += TPB) {
        float v = sStat[i];
        if (v != 0.0f) atomicAdd(&g_stats[i], (double)v);
    }
}

// Per-group Pearson |r|, mean over groups -> coeff. Re-zeroes g_stats after
// consuming it so the next launch/replay starts from identical state.
__global__ __launch_bounds__(NGROUP)
void finalize_kernel(float* __restrict__ coeff_out)
{
    __shared__ double red[NGROUP];
    int g = threadIdx.x;

    double n   = g_stats[0 * NGROUP + g];
    double Sx  = g_stats[1 * NGROUP + g];
    double Sy  = g_stats[2 * NGROUP + g];
    double Sxx = g_stats[3 * NGROUP + g];
    double Syy = g_stats[4 * NGROUP + g];
    double Sxy = g_stats[5 * NGROUP + g];

    double nom = Sxy - Sx * Sy / n;
    double dx  = Sxx - Sx * Sx / n;
    double dy  = Syy - Sy * Sy / n;
    double r   = fabs(nom / sqrt(dx * dy));

    red[g] = r;

    // Reset stats for the next replay (all reads above are complete per-thread;
    // each thread zeroes exactly the entries it read)
    #pragma unroll
    for (int s = 0; s < NSTAT; s++) g_stats[s * NGROUP + g] = 0.0;

    __syncthreads();
    #pragma unroll
    for (int ofs = NGROUP / 2; ofs > 0; ofs >>= 1) {
        if (g < ofs) red[g] += red[g + ofs];
        __syncthreads();
    }
    if (g == 0 && coeff_out) coeff_out[0] = (float)(red[0] / (double)NGROUP);
}

extern "C" void kernel_launch(void* const* d_in, const int* in_sizes, int n_in,
                              void* d_out, int out_size)
{
    const float* X1   = (const float*)d_in[0];
    const float* X2   = (const float*)d_in[1];
    const float* Y    = (const float*)d_in[2];
    const float* W    = (const float*)d_in[3];
    const int*   mask = (const int*)  d_in[4];

    int T = in_sizes[0] / D;

    float* out = (float*)d_out;
    float* coeff_out = nullptr;
    float* pred_out  = nullptr;
    if (out_size == T + 1) {            // (coeff, pred) flattened in return order
        coeff_out = out;
        pred_out  = out + 1;
    } else if (out_size == T) {         // pred only
        pred_out  = out;
    } else {                            // coeff only
        coeff_out = out;
    }

    int numTiles = (T + ROWS - 1) / ROWS;
    int grid = numTiles < MAX_GRID ? numTiles : MAX_GRID;
    pred_stats_kernel<<<grid, TPB>>>((const float4*)X1, (const float4*)X2,
                                     Y, W, mask, pred_out, T, numTiles);

    finalize_kernel<<<1, NGROUP>>>(coeff_out);
}

// round 10
// speedup vs baseline: 1.0652x; 1.0652x over previous
#include <cuda_runtime.h>
#include <math.h>

// Problem geometry (fixed by reference): T=1e6, D=82, 256 groups
#define D        82
#define NGROUP   256
#define TPB      96           // 3 warps per block
#define WPB      3
#define WCHUNK   32           // rows per warp-chunk (one row per lane)
#define SLICE    (WCHUNK * D) // 2624 floats = 10.25 KB per warp
#define BLOCKS_PER_SM 7
#define MAX_GRID  (148 * BLOCKS_PER_SM)   // 1036

// Per-group stats, one 128-byte L2 line per group (spreads atomic traffic
// across LTS slices). Layout: [group][32], slots 0..5 used:
//   0=count 1=Sx 2=Sy 3=Sxx 4=Syy 5=Sxy
// Zero-initialized at module load; finalize_kernel re-zeroes after reading
// so every launch/replay starts from identical state.
__device__ float g_statsF[NGROUP * 32];

// Warp-autonomous kernel: each warp grid-strides over 32-row chunks.
// Stage: lanes cooperatively stream the chunk (coalesced float4 LDGs),
// square diffs into the warp's private smem slice. __syncwarp. Compute:
// each lane dots its own row against sW, sqrt, writes pred, and fires 6
// global RED.ADD.F32 (no return -> fire-and-forget, no SM-side atomic port
// pressure, no block barriers anywhere in the loop).
__global__ __launch_bounds__(TPB, BLOCKS_PER_SM)
void pred_stats_kernel(const float* __restrict__ X1,
                       const float* __restrict__ X2,
                       const float* __restrict__ Y,
                       const float* __restrict__ W,
                       const int*   __restrict__ mask,
                       float* __restrict__ pred_out,   // may be null
                       int T, int numChunks, int totalWarps)
{
    __shared__ __align__(16) float sDiff[WPB][SLICE];  // 30.75 KB
    __shared__ float sW[D];

    const int tid  = threadIdx.x;
    const int wid  = tid >> 5;
    const int lane = tid & 31;
    const int gwarp = blockIdx.x * WPB + wid;

    if (tid < D) sW[tid] = W[tid];
    __syncthreads();                      // sW visible to all warps

    float* const slice = sDiff[wid];

    for (int c = gwarp; c < numChunks; c += totalWarps) {
        const int row0 = c * WCHUNK;
        const int rows = min(WCHUNK, T - row0);
        const int r    = row0 + lane;

        // Early per-row loads (overlap with the staging stream)
        float yReg = 0.0f; int gReg = 0;
        if (lane < rows) { yReg = Y[r]; gReg = mask[r]; }

        if (rows == WCHUNK) {
            // Full chunk: 656 float4s, coalesced within the warp
            const float4* __restrict__ A =
                reinterpret_cast<const float4*>(X1 + (size_t)row0 * D);
            const float4* __restrict__ B =
                reinterpret_cast<const float4*>(X2 + (size_t)row0 * D);
            float4* __restrict__ S = reinterpret_cast<float4*>(slice);

            #pragma unroll
            for (int k = 0; k < SLICE / 4 / 32; k++) {     // 20 full iters
                const int i = lane + k * 32;
                float4 a = A[i];
                float4 b = B[i];
                float4 d;
                d.x = a.x - b.x; d.x *= d.x;
                d.y = a.y - b.y; d.y *= d.y;
                d.z = a.z - b.z; d.z *= d.z;
                d.w = a.w - b.w; d.w *= d.w;
                S[i] = d;
            }
            {   // remainder: 656 - 640 = 16 float4s
                const int i = 640 + lane;
                if (lane < 16) {
                    float4 a = A[i];
                    float4 b = B[i];
                    float4 d;
                    d.x = a.x - b.x; d.x *= d.x;
                    d.y = a.y - b.y; d.y *= d.y;
                    d.z = a.z - b.z; d.z *= d.z;
                    d.w = a.w - b.w; d.w *= d.w;
                    S[i] = d;
                }
            }
        } else {
            // Tail chunk: float2 granularity (rows*82 always even)
            const int n2 = rows * (D / 2);
            const float2* __restrict__ A =
                reinterpret_cast<const float2*>(X1 + (size_t)row0 * D);
            const float2* __restrict__ B =
                reinterpret_cast<const float2*>(X2 + (size_t)row0 * D);
            float2* __restrict__ S = reinterpret_cast<float2*>(slice);
            for (int i = lane; i < n2; i += 32) {
                float2 a = A[i];
                float2 b = B[i];
                float2 d;
                d.x = a.x - b.x; d.x *= d.x;
                d.y = a.y - b.y; d.y *= d.y;
                S[i] = d;
            }
        }
        __syncwarp();

        // Compute: one row per lane (2-way bank conflict max on LDS.64)
        if (lane < rows) {
            const float2* __restrict__ dd =
                reinterpret_cast<const float2*>(slice + lane * D);
            float s = 0.0f;
            #pragma unroll
            for (int i = 0; i < D / 2; i++) {
                float2 v = dd[i];
                s = fmaf(v.x, sW[2 * i],     s);
                s = fmaf(v.y, sW[2 * i + 1], s);
            }
            float x = sqrtf(s);
            if (pred_out) pred_out[r] = x;

            // Fire-and-forget global reductions (RED.ADD.F32, no return)
            float* st = g_statsF + (gReg << 5);
            atomicAdd(st + 0, 1.0f);
            atomicAdd(st + 1, x);
            atomicAdd(st + 2, yReg);
            atomicAdd(st + 3, s);           // x*x == s (to rounding)
            atomicAdd(st + 4, yReg * yReg);
            atomicAdd(st + 5, x * yReg);
        }
        __syncwarp();   // all lanes done reading slice before next overwrite
    }
}

// Per-group Pearson |r|, mean over groups -> coeff. Re-zeroes g_statsF after
// consuming it so the next launch/replay starts from identical state.
__global__ __launch_bounds__(NGROUP)
void finalize_kernel(float* __restrict__ coeff_out)
{
    __shared__ double red[NGROUP];
    int g = threadIdx.x;

    const float* st = g_statsF + (g << 5);
    double n   = st[0];
    double Sx  = st[1];
    double Sy  = st[2];
    double Sxx = st[3];
    double Syy = st[4];
    double Sxy = st[5];

    double nom = Sxy - Sx * Sy / n;
    double dx  = Sxx - Sx * Sx / n;
    double dy  = Syy - Sy * Sy / n;
    double r   = fabs(nom / sqrt(dx * dy));

    red[g] = r;

    // Reset for next replay (each thread zeroes exactly what it read)
    float* stw = g_statsF + (g << 5);
    #pragma unroll
    for (int s = 0; s < 6; s++) stw[s] = 0.0f;

    __syncthreads();
    #pragma unroll
    for (int ofs = NGROUP / 2; ofs > 0; ofs >>= 1) {
        if (g < ofs) red[g] += red[g + ofs];
        __syncthreads();
    }
    if (g == 0 && coeff_out) coeff_out[0] = (float)(red[0] / (double)NGROUP);
}

extern "C" void kernel_launch(void* const* d_in, const int* in_sizes, int n_in,
                              void* d_out, int out_size)
{
    const float* X1   = (const float*)d_in[0];
    const float* X2   = (const float*)d_in[1];
    const float* Y    = (const float*)d_in[2];
    const float* W    = (const float*)d_in[3];
    const int*   mask = (const int*)  d_in[4];

    int T = in_sizes[0] / D;

    float* out = (float*)d_out;
    float* coeff_out = nullptr;
    float* pred_out  = nullptr;
    if (out_size == T + 1) {            // (coeff, pred) flattened in return order
        coeff_out = out;
        pred_out  = out + 1;
    } else if (out_size == T) {         // pred only
        pred_out  = out;
    } else {                            // coeff only
        coeff_out = out;
    }

    int numChunks = (T + WCHUNK - 1) / WCHUNK;
    int grid = MAX_GRID;
    int totalWarps = grid * WPB;
    pred_stats_kernel<<<grid, TPB>>>(X1, X2, Y, W, mask, pred_out,
                                     T, numChunks, totalWarps);

    finalize_kernel<<<1, NGROUP>>>(coeff_out);
}

// round 11
// speedup vs baseline: 1.1292x; 1.0601x over previous
#include <cuda_runtime.h>
#include <math.h>

// Problem geometry (fixed by reference): T=1e6, D=82, 256 groups
#define D        82
#define NGROUP   256
#define NSTAT    6            // count, Sx, Sy, Sxx, Syy, Sxy
#define TPB      96           // threads per block == rows per tile
#define ROWS     96
#define TILE_ELEMS (ROWS * D)        // 7872 floats = 31.5 KB
#define TILE_V4    (TILE_ELEMS / 4)  // 1968 float4
#define FULL_ITERS (TILE_V4 / TPB)   // 20 (tail: 48 threads)
#define BLOCKS_PER_SM 6
#define MAX_GRID   (148 * BLOCKS_PER_SM)   // 888

// Zero-initialized at module load; the last block resets both after use so
// every launch / graph replay starts from identical state.
__device__ double   g_stats[NSTAT * NGROUP];
__device__ unsigned g_ticket;

// Single fused persistent kernel (exact R3 hot-loop structure, which
// benched best at 145.9us):
//   - coalesced float4 streaming -> fp32 shared staging of (X1-X2)^2
//   - per-thread row dot with W, sqrt, pred store
//   - 6 fp32 shared atomics per row (per-block partials, fp32 exact enough;
//     promoted to double at the single per-block global flush)
//   - last-block ticket: finalize (per-group Pearson |r|, mean, coeff) runs
//     inside this kernel -> no separate finalize/zero launches.
__global__ __launch_bounds__(TPB, BLOCKS_PER_SM)
void fused_stsim_kernel(const float4* __restrict__ X1,
                        const float4* __restrict__ X2,
                        const float*  __restrict__ Y,
                        const float*  __restrict__ W,
                        const int*    __restrict__ mask,
                        float* __restrict__ pred_out,   // may be null
                        float* __restrict__ coeff_out,  // may be null
                        int T, int numTiles)
{
    __shared__ __align__(16) float sDiff[TILE_ELEMS];  // 31.5 KB (reused below)
    __shared__ float sStat[NSTAT * NGROUP];            // 6 KB
    __shared__ float sW[D];                            // 328 B
    __shared__ unsigned isLast;

    const int tid = threadIdx.x;

    for (int i = tid; i < NSTAT * NGROUP; i += TPB) sStat[i] = 0.0f;
    if (tid < D) sW[tid] = W[tid];
    // first-iteration __syncthreads below covers this init

    for (int tile = blockIdx.x; tile < numTiles; tile += gridDim.x) {
        const int row0 = tile * ROWS;
        const int rows = min(ROWS, T - row0);
        const int t    = row0 + tid;
        const size_t base4 = (size_t)row0 * D / 4;   // float4-aligned

        __syncthreads();   // prior phase-2 reads done before overwrite (and init)

        // Prefetch this row's Y/mask during the streaming phase
        float yReg = 0.0f; int gReg = 0;
        if (tid < rows) { yReg = Y[t]; gReg = mask[t]; }

        const float4* __restrict__ A = X1 + base4;
        const float4* __restrict__ B = X2 + base4;
        float4* __restrict__ S4 = reinterpret_cast<float4*>(sDiff);

        if (rows == ROWS) {
            // Full tile: fixed trip count, fully unrolled -> batched LDG.128s
            int i = tid;
            #pragma unroll
            for (int k = 0; k < FULL_ITERS; k++, i += TPB) {
                float4 a = A[i];
                float4 b = B[i];
                float4 d;
                d.x = a.x - b.x; d.x *= d.x;
                d.y = a.y - b.y; d.y *= d.y;
                d.z = a.z - b.z; d.z *= d.z;
                d.w = a.w - b.w; d.w *= d.w;
                S4[i] = d;
            }
            if (i < TILE_V4) {                       // tail: 48 threads
                float4 a = A[i];
                float4 b = B[i];
                float4 d;
                d.x = a.x - b.x; d.x *= d.x;
                d.y = a.y - b.y; d.y *= d.y;
                d.z = a.z - b.z; d.z *= d.z;
                d.w = a.w - b.w; d.w *= d.w;
                S4[i] = d;
            }
        } else {
            const int n4 = (rows * D) / 4;           // rows even -> divisible
            for (int i = tid; i < n4; i += TPB) {
                float4 a = A[i];
                float4 b = B[i];
                float4 d;
                d.x = a.x - b.x; d.x *= d.x;
                d.y = a.y - b.y; d.y *= d.y;
                d.z = a.z - b.z; d.z *= d.z;
                d.w = a.w - b.w; d.w *= d.w;
                S4[i] = d;
            }
        }
        __syncthreads();

        // Phase 2: one row per thread (shared reads, 2-way conflict max)
        if (tid < rows) {
            const float2* __restrict__ dd =
                reinterpret_cast<const float2*>(sDiff + tid * D);  // 8B aligned
            float s = 0.0f;
            #pragma unroll
            for (int i = 0; i < D / 2; i++) {
                float2 v = dd[i];
                s = fmaf(v.x, sW[2 * i],     s);
                s = fmaf(v.y, sW[2 * i + 1], s);
            }
            float x = sqrtf(s);
            if (pred_out) pred_out[t] = x;

            const int g = gReg;
            const float y = yReg;
            atomicAdd(&sStat[0 * NGROUP + g], 1.0f);
            atomicAdd(&sStat[1 * NGROUP + g], x);
            atomicAdd(&sStat[2 * NGROUP + g], y);
            atomicAdd(&sStat[3 * NGROUP + g], s);       // x*x == s (to rounding)
            atomicAdd(&sStat[4 * NGROUP + g], y * y);
            atomicAdd(&sStat[5 * NGROUP + g], x * y);
        }
    }

    __syncthreads();
    // One flush per persistent block: promote float partials to global doubles
    for (int i = tid; i < NSTAT * NGROUP; i += TPB) {
        float v = sStat[i];
        if (v != 0.0f) atomicAdd(&g_stats[i], (double)v);
    }

    // ---- last-block finalize (replaces the separate finalize kernel) ----
    __threadfence();   // make this block's g_stats adds visible before ticket
    if (tid == 0)
        isLast = (atomicAdd(&g_ticket, 1u) == (unsigned)(gridDim.x - 1)) ? 1u : 0u;
    __syncthreads();

    if (isLast) {
        // sDiff is dead here; overlay the reduction scratch on it (keeps the
        // 6-blocks/SM smem budget intact).
        double* red = reinterpret_cast<double*>(sDiff);   // 96 doubles, 16B-aligned

        double acc = 0.0;
        for (int g = tid; g < NGROUP; g += TPB) {
            const double n   = __ldcg(&g_stats[0 * NGROUP + g]);
            const double Sx  = __ldcg(&g_stats[1 * NGROUP + g]);
            const double Sy  = __ldcg(&g_stats[2 * NGROUP + g]);
            const double Sxx = __ldcg(&g_stats[3 * NGROUP + g]);
            const double Syy = __ldcg(&g_stats[4 * NGROUP + g]);
            const double Sxy = __ldcg(&g_stats[5 * NGROUP + g]);

            const double nom = Sxy - Sx * Sy / n;
            const double dx  = Sxx - Sx * Sx / n;
            const double dy  = Syy - Sy * Sy / n;
            acc += fabs(nom / sqrt(dx * dy));

            // Reset for the next launch/replay
            #pragma unroll
            for (int s = 0; s < NSTAT; s++) g_stats[s * NGROUP + g] = 0.0;
        }
        red[tid] = acc;
        __syncthreads();

        if (tid < 32) {
            double a = red[tid] + red[tid + 32] + red[tid + 64];
            #pragma unroll
            for (int ofs = 16; ofs > 0; ofs >>= 1)
                a += __shfl_down_sync(0xFFFFFFFFu, a, ofs);
            if (tid == 0) {
                if (coeff_out) coeff_out[0] = (float)(a / (double)NGROUP);
                g_ticket = 0;   // reset ticket for next launch/replay
            }
        }
    }
}

extern "C" void kernel_launch(void* const* d_in, const int* in_sizes, int n_in,
                              void* d_out, int out_size)
{
    const float* X1   = (const float*)d_in[0];
    const float* X2   = (const float*)d_in[1];
    const float* Y    = (const float*)d_in[2];
    const float* W    = (const float*)d_in[3];
    const int*   mask = (const int*)  d_in[4];

    int T = in_sizes[0] / D;

    float* out = (float*)d_out;
    float* coeff_out = nullptr;
    float* pred_out  = nullptr;
    if (out_size == T + 1) {            // (coeff, pred) flattened in return order
        coeff_out = out;
        pred_out  = out + 1;
    } else if (out_size == T) {         // pred only
        pred_out  = out;
    } else {                            // coeff only
        coeff_out = out;
    }

    int numTiles = (T + ROWS - 1) / ROWS;
    int grid = numTiles < MAX_GRID ? numTiles : MAX_GRID;
    fused_stsim_kernel<<<grid, TPB>>>((const float4*)X1, (const float4*)X2,
                                      Y, W, mask, pred_out, coeff_out,
                                      T, numTiles);
}

// round 12
// speedup vs baseline: 1.1595x; 1.0269x over previous
#include <cuda_runtime.h>
#include <math.h>

// Problem geometry (fixed by reference): T=1e6, D=82, 256 groups
#define D        82
#define NGROUP   256
#define NSTAT    6            // count, Sx, Sy, Sxx, Syy, Sxy
#define TPB      96           // threads per block == rows per tile
#define ROWS     96
#define SLOTS    21           // weighted partials per row (20 full float4 + straddle)
#define N4_TILE  (ROWS * D / 4)      // 1968 float4 per full tile
#define MAX_GRID (148 * 14)          // 2072 (smem allows ~14 blocks/SM)

// Zero-initialized at module load; the last block resets both after use so
// every launch / graph replay starts from identical state.
__device__ double   g_stats[NSTAT * NGROUP];
__device__ unsigned g_ticket;

// Fused persistent kernel with WEIGHTED-PARTIAL staging:
// phase 1 streams float4 pairs (coalesced LDG.128) and stores ONE float per
// float4 -- the W-weighted squared-diff partial -- into sPart[row][slot].
// The 82-float row pattern repeats every 41 float4s (2 rows); float4 q==20
// straddles a row boundary and splits lo/hi. Phase 2: each thread sums its
// row's 21 partials, sqrt, pred store, 6 fp32 shared atomics.
// smem ~15.2KB/block -> ~14 blocks/SM (vs 5 before): staggered blocks keep
// DRAM busy continuously. Last-block ticket runs the Pearson finalize.
__global__ __launch_bounds__(TPB, 10)
void fused_stsim_kernel(const float4* __restrict__ X1,
                        const float4* __restrict__ X2,
                        const float*  __restrict__ Y,
                        const float*  __restrict__ W,
                        const int*    __restrict__ mask,
                        float* __restrict__ pred_out,   // may be null
                        float* __restrict__ coeff_out,  // may be null
                        int T, int numTiles)
{
    __shared__ float  sPart[ROWS * SLOTS];   // 8064 B
    __shared__ float  sStat[NSTAT * NGROUP]; // 6144 B
    __shared__ float  sW[D];                 // 328 B
    __shared__ __align__(16) float4 sW4[41]; // 656 B: per-float4 weight vectors
    __shared__ unsigned isLast;

    const int tid = threadIdx.x;

    for (int i = tid; i < NSTAT * NGROUP; i += TPB) sStat[i] = 0.0f;
    if (tid < D) sW[tid] = W[tid];
    __syncthreads();

    // Build the 41-entry weight table (pattern of W across 2 rows of float4s)
    if (tid < 41) {
        float4 w;
        if (tid < 20) {
            const int e = 4 * tid;
            w.x = sW[e]; w.y = sW[e + 1]; w.z = sW[e + 2]; w.w = sW[e + 3];
        } else if (tid == 20) {          // straddler: row els 80,81 | 0,1
            w.x = sW[80]; w.y = sW[81]; w.z = sW[0]; w.w = sW[1];
        } else {                          // q=21..40: next-row els 2..81
            const int e = 4 * (tid - 21) + 2;
            w.x = sW[e]; w.y = sW[e + 1]; w.z = sW[e + 2]; w.w = sW[e + 3];
        }
        sW4[tid] = w;
    }
    // first-iteration __syncthreads below makes sW4 visible

    for (int tile = blockIdx.x; tile < numTiles; tile += gridDim.x) {
        const int row0 = tile * ROWS;     // always even
        const int rows = min(ROWS, T - row0);
        const int t    = row0 + tid;
        const size_t base4 = (size_t)row0 * D / 4;

        __syncthreads();   // prior phase-2 reads done; first iter: init visible

        // Prefetch this row's Y/mask during the streaming phase
        float yReg = 0.0f; int gReg = 0;
        if (tid < rows) { yReg = Y[t]; gReg = mask[t]; }

        const float4* __restrict__ A = X1 + base4;
        const float4* __restrict__ B = X2 + base4;
        const int n4 = (rows * D) / 4;   // rows always even -> integer

        #pragma unroll 4
        for (int i = tid; i < n4; i += TPB) {
            float4 a = A[i];
            float4 b = B[i];
            const int p = i / 41;        // row pair index
            const int q = i - p * 41;    // position within the 2-row pattern
            float4 w = sW4[q];

            float d0 = a.x - b.x, d1 = a.y - b.y;
            float d2 = a.z - b.z, d3 = a.w - b.w;
            float t0 = d0 * d0, t1 = d1 * d1;
            float t2 = d2 * d2, t3 = d3 * d3;

            if (q != 20) {
                float partial = fmaf(t3, w.w,
                                fmaf(t2, w.z,
                                fmaf(t1, w.y, t0 * w.x)));
                const int row  = 2 * p + (q > 20);
                const int slot = (q < 20) ? q : (q - 20);
                sPart[row * SLOTS + slot] = partial;
            } else {                      // straddler: split lo/hi
                sPart[(2 * p) * SLOTS + 20]    = fmaf(t1, w.y, t0 * w.x);
                sPart[(2 * p + 1) * SLOTS + 0] = fmaf(t3, w.w, t2 * w.z);
            }
        }
        __syncthreads();

        // Phase 2: one row per thread; 21 conflict-free LDS.32 (stride 21)
        if (tid < rows) {
            const float* __restrict__ pr = sPart + tid * SLOTS;
            float s0 = 0.0f, s1 = 0.0f, s2 = 0.0f;
            #pragma unroll
            for (int j = 0; j < 18; j += 3) {
                s0 += pr[j]; s1 += pr[j + 1]; s2 += pr[j + 2];
            }
            s0 += pr[18]; s1 += pr[19]; s2 += pr[20];
            const float s = s0 + s1 + s2;

            const float x = sqrtf(s);
            if (pred_out) pred_out[t] = x;

            const int g = gReg;
            const float y = yReg;
            atomicAdd(&sStat[0 * NGROUP + g], 1.0f);
            atomicAdd(&sStat[1 * NGROUP + g], x);
            atomicAdd(&sStat[2 * NGROUP + g], y);
            atomicAdd(&sStat[3 * NGROUP + g], s);       // x*x == s (to rounding)
            atomicAdd(&sStat[4 * NGROUP + g], y * y);
            atomicAdd(&sStat[5 * NGROUP + g], x * y);
        }
    }

    __syncthreads();
    // One flush per block: promote float partials to global doubles
    for (int i = tid; i < NSTAT * NGROUP; i += TPB) {
        float v = sStat[i];
        if (v != 0.0f) atomicAdd(&g_stats[i], (double)v);
    }

    // ---- last-block finalize ----
    __threadfence();
    if (tid == 0)
        isLast = (atomicAdd(&g_ticket, 1u) == (unsigned)(gridDim.x - 1)) ? 1u : 0u;
    __syncthreads();

    if (isLast) {
        // sPart is dead; overlay reduction scratch
        double* red = reinterpret_cast<double*>(sPart);

        double acc = 0.0;
        for (int g = tid; g < NGROUP; g += TPB) {
            const double n   = __ldcg(&g_stats[0 * NGROUP + g]);
            const double Sx  = __ldcg(&g_stats[1 * NGROUP + g]);
            const double Sy  = __ldcg(&g_stats[2 * NGROUP + g]);
            const double Sxx = __ldcg(&g_stats[3 * NGROUP + g]);
            const double Syy = __ldcg(&g_stats[4 * NGROUP + g]);
            const double Sxy = __ldcg(&g_stats[5 * NGROUP + g]);

            const double nom = Sxy - Sx * Sy / n;
            const double dx  = Sxx - Sx * Sx / n;
            const double dy  = Syy - Sy * Sy / n;
            acc += fabs(nom / sqrt(dx * dy));

            #pragma unroll
            for (int s = 0; s < NSTAT; s++) g_stats[s * NGROUP + g] = 0.0;
        }
        red[tid] = acc;
        __syncthreads();

        if (tid < 32) {
            double a = red[tid] + red[tid + 32] + red[tid + 64];
            #pragma unroll
            for (int ofs = 16; ofs > 0; ofs >>= 1)
                a += __shfl_down_sync(0xFFFFFFFFu, a, ofs);
            if (tid == 0) {
                if (coeff_out) coeff_out[0] = (float)(a / (double)NGROUP);
                g_ticket = 0;   // reset for next launch/replay
            }
        }
    }
}

extern "C" void kernel_launch(void* const* d_in, const int* in_sizes, int n_in,
                              void* d_out, int out_size)
{
    const float* X1   = (const float*)d_in[0];
    const float* X2   = (const float*)d_in[1];
    const float* Y    = (const float*)d_in[2];
    const float* W    = (const float*)d_in[3];
    const int*   mask = (const int*)  d_in[4];

    int T = in_sizes[0] / D;

    float* out = (float*)d_out;
    float* coeff_out = nullptr;
    float* pred_out  = nullptr;
    if (out_size == T + 1) {            // (coeff, pred) flattened in return order
        coeff_out = out;
        pred_out  = out + 1;
    } else if (out_size == T) {         // pred only
        pred_out  = out;
    } else {                            // coeff only
        coeff_out = out;
    }

    int numTiles = (T + ROWS - 1) / ROWS;
    int grid = numTiles < MAX_GRID ? numTiles : MAX_GRID;
    fused_stsim_kernel<<<grid, TPB>>>((const float4*)X1, (const float4*)X2,
                                      Y, W, mask, pred_out, coeff_out,
                                      T, numTiles);
}

// round 14
// speedup vs baseline: 1.2481x; 1.0764x over previous
#include <cuda_runtime.h>
#include <math.h>

// Problem geometry (fixed by reference): T=1e6, D=82, 256 groups
#define D        82
#define NGROUP   256
#define NSTAT    6            // count, Sx, Sy, Sxx, Syy, Sxy
#define TPB      96           // threads per block == rows per tile
#define ROWS     96
#define SLOTS    21           // weighted partials per row
#define BLOCKS_PER_SM 9
#define MAX_GRID (148 * BLOCKS_PER_SM)   // 1332

// fp32 global stat accumulators (cross-block partial sums; ~2e-6 rel err,
// amplified ~30x in the Pearson cancellation -> ~6e-5, well under 1e-3).
// Zero-initialized at module load; last block resets after use.
__device__ float    g_stats[NSTAT * NGROUP];
__device__ unsigned g_ticket;

// Fused persistent kernel: weighted-partial staging + cheap double buffering.
// Stage of tile k+1 issues its coalesced LDG.128s BEFORE phase 2 of tile k,
// so each block streams DRAM continuously; 8KB buffers keep 9 blocks x 3
// warps = 27 warps/SM resident. Last-block ticket finalizes in-kernel.
__global__ __launch_bounds__(TPB, BLOCKS_PER_SM)
void fused_stsim_kernel(const float4* __restrict__ X1,
                        const float4* __restrict__ X2,
                        const float*  __restrict__ Y,
                        const float*  __restrict__ W,
                        const int*    __restrict__ mask,
                        float* __restrict__ pred_out,   // may be null
                        float* __restrict__ coeff_out,  // may be null
                        int T, int numTiles)
{
    __shared__ float  sPart[2][ROWS * SLOTS];  // 2 x 8064 B
    __shared__ float  sStat[NSTAT * NGROUP];   // 6144 B
    __shared__ float  sW[D];                   // 328 B
    __shared__ __align__(16) float4 sW4[41];   // 656 B
    __shared__ unsigned isLast;

    const int tid = threadIdx.x;

    if (tid == 0) isLast = 0u;
    for (int i = tid; i < NSTAT * NGROUP; i += TPB) sStat[i] = 0.0f;
    if (tid < D) sW[tid] = W[tid];
    __syncthreads();

    // 41-entry weight table: W pattern across 2 rows of float4s.
    if (tid < 41) {
        float4 w;
        if (tid < 20) {
            const int e = 4 * tid;
            w.x = sW[e]; w.y = sW[e + 1]; w.z = sW[e + 2]; w.w = sW[e + 3];
        } else if (tid == 20) {          // straddler: row els 80,81 | 0,1
            w.x = sW[80]; w.y = sW[81]; w.z = sW[0]; w.w = sW[1];
        } else {                          // q=21..40: next-row els 2..81
            const int e = 4 * (tid - 21) + 2;
            w.x = sW[e]; w.y = sW[e + 1]; w.z = sW[e + 2]; w.w = sW[e + 3];
        }
        sW4[tid] = w;
    }
    __syncthreads();

    // ---- stage helper: weighted partials of (X1-X2)^2 into sPart[buf] ----
#define STAGE(tileIdx, buf)                                                   \
    do {                                                                      \
        const int _row0 = (tileIdx) * ROWS;                                   \
        const int _rows = min(ROWS, T - _row0);                               \
        const int _n4   = (_rows * D) / 4;                                    \
        const float4* __restrict__ _A = X1 + (size_t)_row0 * D / 4;           \
        const float4* __restrict__ _B = X2 + (size_t)_row0 * D / 4;           \
        float* __restrict__ _S = sPart[buf];                                  \
        _Pragma("unroll 4")                                                   \
        for (int _i = tid; _i < _n4; _i += TPB) {                             \
            float4 _a = _A[_i];                                               \
            float4 _b = _B[_i];                                               \
            const int _p = _i / 41;                                           \
            const int _q = _i - _p * 41;                                      \
            float4 _w = sW4[_q];                                              \
            float _d0 = _a.x - _b.x, _d1 = _a.y - _b.y;                       \
            float _d2 = _a.z - _b.z, _d3 = _a.w - _b.w;                       \
            float _t0 = _d0 * _d0, _t1 = _d1 * _d1;                           \
            float _t2 = _d2 * _d2, _t3 = _d3 * _d3;                           \
            if (_q != 20) {                                                   \
                float _pa = fmaf(_t3, _w.w, fmaf(_t2, _w.z,                   \
                            fmaf(_t1, _w.y, _t0 * _w.x)));                    \
                const int _row  = 2 * _p + (_q > 20);                         \
                const int _slot = (_q < 20) ? _q : (_q - 20);                 \
                _S[_row * SLOTS + _slot] = _pa;                               \
            } else {                                                          \
                _S[(2 * _p) * SLOTS + 20]    = fmaf(_t1, _w.y, _t0 * _w.x);   \
                _S[(2 * _p + 1) * SLOTS + 0] = fmaf(_t3, _w.w, _t2 * _w.z);   \
            }                                                                 \
        }                                                                     \
    } while (0)

    const int firstTile = blockIdx.x;
    if (firstTile < numTiles) STAGE(firstTile, 0);   // prologue

    int k = 0;
    for (int tile = firstTile; tile < numTiles; tile += gridDim.x, k++) {
        const int cur  = k & 1;
        const int row0 = tile * ROWS;
        const int rows = min(ROWS, T - row0);
        const int t    = row0 + tid;

        __syncthreads();   // buf[cur] fully staged; prior reads of buf[cur^1] done

        // This tile's Y/mask loads issue early (overlap with staging below)
        float yReg = 0.0f; int gReg = 0;
        if (tid < rows) { yReg = Y[t]; gReg = mask[t]; }

        // Stage NEXT tile into the other buffer (LDGs go out first)
        const int nextTile = tile + gridDim.x;
        if (nextTile < numTiles) STAGE(nextTile, cur ^ 1);

        // Compute current tile: one row per thread; 21 conflict-free LDS.32
        if (tid < rows) {
            const float* __restrict__ pr = sPart[cur] + tid * SLOTS;
            float s0 = 0.0f, s1 = 0.0f, s2 = 0.0f;
            #pragma unroll
            for (int j = 0; j < 18; j += 3) {
                s0 += pr[j]; s1 += pr[j + 1]; s2 += pr[j + 2];
            }
            s0 += pr[18]; s1 += pr[19]; s2 += pr[20];
            const float s = s0 + s1 + s2;

            const float x = sqrtf(s);
            if (pred_out) pred_out[t] = x;

            const int g = gReg;
            const float y = yReg;
            atomicAdd(&sStat[0 * NGROUP + g], 1.0f);
            atomicAdd(&sStat[1 * NGROUP + g], x);
            atomicAdd(&sStat[2 * NGROUP + g], y);
            atomicAdd(&sStat[3 * NGROUP + g], s);       // x*x == s (to rounding)
            atomicAdd(&sStat[4 * NGROUP + g], y * y);
            atomicAdd(&sStat[5 * NGROUP + g], x * y);
        }
    }
#undef STAGE

    __syncthreads();
    // One flush per block: fp32 global atomics
    for (int i = tid; i < NSTAT * NGROUP; i += TPB) {
        float v = sStat[i];
        if (v != 0.0f) atomicAdd(&g_stats[i], v);
    }

    // ---- last-block finalize ----
    __threadfence();
    if (tid == 0) {
        if (atomicAdd(&g_ticket, 1u) == (unsigned)(gridDim.x - 1)) isLast = 1u;
    }
    __syncthreads();

    if (isLast) {
        double* red = reinterpret_cast<double*>(sPart[0]);  // dead buffer

        double acc = 0.0;
        for (int g = tid; g < NGROUP; g += TPB) {
            const double n   = (double)__ldcg(&g_stats[0 * NGROUP + g]);
            const double Sx  = (double)__ldcg(&g_stats[1 * NGROUP + g]);
            const double Sy  = (double)__ldcg(&g_stats[2 * NGROUP + g]);
            const double Sxx = (double)__ldcg(&g_stats[3 * NGROUP + g]);
            const double Syy = (double)__ldcg(&g_stats[4 * NGROUP + g]);
            const double Sxy = (double)__ldcg(&g_stats[5 * NGROUP + g]);

            const double nom = Sxy - Sx * Sy / n;
            const double dx  = Sxx - Sx * Sx / n;
            const double dy  = Syy - Sy * Sy / n;
            acc += fabs(nom / sqrt(dx * dy));

            #pragma unroll
            for (int s = 0; s < NSTAT; s++) g_stats[s * NGROUP + g] = 0.0f;
        }
        red[tid] = acc;
        __syncthreads();

        if (tid < 32) {
            double a = red[tid] + red[tid + 32] + red[tid + 64];
            #pragma unroll
            for (int ofs = 16; ofs > 0; ofs >>= 1)
                a += __shfl_down_sync(0xFFFFFFFFu, a, ofs);
            if (tid == 0) {
                if (coeff_out) coeff_out[0] = (float)(a / (double)NGROUP);
                g_ticket = 0;   // reset for next launch/replay
            }
        }
    }
}

extern "C" void kernel_launch(void* const* d_in, const int* in_sizes, int n_in,
                              void* d_out, int out_size)
{
    const float* X1   = (const float*)d_in[0];
    const float* X2   = (const float*)d_in[1];
    const float* Y    = (const float*)d_in[2];
    const float* W    = (const float*)d_in[3];
    const int*   mask = (const int*)  d_in[4];

    int T = in_sizes[0] / D;

    float* out = (float*)d_out;
    float* coeff_out = nullptr;
    float* pred_out  = nullptr;
    if (out_size == T + 1) {            // (coeff, pred) flattened in return order
        coeff_out = out;
        pred_out  = out + 1;
    } else if (out_size == T) {         // pred only
        pred_out  = out;
    } else {                            // coeff only
        coeff_out = out;
    }

    int numTiles = (T + ROWS - 1) / ROWS;
    int grid = numTiles < MAX_GRID ? numTiles : MAX_GRID;
    fused_stsim_kernel<<<grid, TPB>>>((const float4*)X1, (const float4*)X2,
                                      Y, W, mask, pred_out, coeff_out,
                                      T, numTiles);
}